// round 5
// baseline (speedup 1.0000x reference)
#include <cuda_runtime.h>
#include <math.h>

#define NH 8
#define SEQ 32
#define DK 8
#define DM 64
#define PI_F 3.14159265358979323846f
#define W_MUL 0.6324555320336759f  // sqrt(2/5)

#define WPAD 65                    // padded W-table row, in float2
#define NWARP 8                    // chains per block
#define GRID 32                    // NH * 32 / NWARP

// dynamic smem layout (bytes):
//   [0, 133120)        W table: [8 warps][32 j][WPAD] float2
//                      (aliased: pre-stage x[32][64], W1[8][64] floats;
//                       later aliased: sz[32][64] floats for the final GEMV)
//   [133120, 141312)   rho: [8 warps][2 buf][64] float2
#define OFF_RHO 133120
#define DYN_BYTES 141312

static __device__ float    g_z[SEQ * NH * DK];   // [s][h*8+e]
static __device__ unsigned g_cnt;                 // zero-init; reset each run

__device__ __forceinline__ float2 cmul(float2 a, float2 b) {
    return make_float2(fmaf(a.x, b.x, -a.y * b.y), fmaf(a.x, b.y, a.y * b.x));
}
// a * conj(b)
__device__ __forceinline__ float2 cmulc(float2 a, float2 b) {
    return make_float2(fmaf(a.x, b.x, a.y * b.y), fmaf(a.y, b.x, -a.x * b.y));
}
__device__ __forceinline__ float2 cadd(float2 a, float2 b) {
    return make_float2(a.x + b.x, a.y + b.y);
}
// acc += a * b (complex)
__device__ __forceinline__ void cmac(float2& acc, float2 a, float2 b) {
    acc.x = fmaf(a.x, b.x, fmaf(-a.y, b.y, acc.x));
    acc.y = fmaf(a.x, b.y, fmaf( a.y, b.x, acc.y));
}

// CNOT-ring basis permutation f(x)
__device__ __forceinline__ int permf(int x) {
#pragma unroll
    for (int t = 0; t < 6; t++) {
        int cb = 5 - t;
        int tb = 5 - ((t + 1) % 6);
        if ((x >> cb) & 1) x ^= (1 << tb);
    }
    return x;
}

// apply 3-qubit kron unitary (u[q][4], qubit 0 = MSB) to real vector psi[8]
__device__ __forceinline__ void apply_u3(const float2 (*u)[4], const float* psi,
                                         float2* v) {
#pragma unroll
    for (int e = 0; e < 8; e++) v[e] = make_float2(psi[e], 0.f);
#pragma unroll
    for (int q = 0; q < 3; q++) {
        int p = 2 - q;
        float2 u0 = u[q][0], u1 = u[q][1], u2 = u[q][2], u3 = u[q][3];
#pragma unroll
        for (int k = 0; k < 8; k++) {
            if ((k >> p) & 1) continue;
            int k1 = k | (1 << p);
            float2 v0 = v[k], v1 = v[k1];
            v[k]  = cadd(cmul(u0, v0), cmul(u1, v1));
            v[k1] = cadd(cmul(u2, v0), cmul(u3, v1));
        }
    }
}

// single fused kernel: grid=32, block=256
// block b: head h = b>>2, chains i = (b&3)*8 + w, w = 0..7
__global__ void __launch_bounds__(256)
qfused(const float* __restrict__ x,     // (32,64)
       const float* __restrict__ pqc,   // (8,3,9)
       const float* __restrict__ W1,    // (8,64)
       const float* __restrict__ b1,    // (8,)
       const float* __restrict__ W2,    // (64,64)
       const float* __restrict__ b2,    // (64,)
       float* __restrict__ out)         // (1,32,64)
{
    extern __shared__ char dyn[];
    float2* Wt    = (float2*)dyn;                 // [w][j][WPAD]
    float2* rho   = (float2*)(dyn + OFF_RHO);     // [w][buf][64]
    float*  pre_x = (float*)dyn;                  // [32][64] (stage)
    float*  pre_w = (float*)(dyn + 8192);         // [8][64]  (stage)
    float*  szf   = (float*)dyn;                  // [32][64] (final GEMV)

    const int h  = blockIdx.x >> 2;
    const int i0 = (blockIdx.x & 3) * NWARP;
    const int t  = threadIdx.x;      // 0..255
    const int w  = t >> 5;           // warp = chain
    const int l  = t & 31;

    __shared__ float  s_xq [SEQ][DK];
    __shared__ float  s_psi[SEQ][DK];
    __shared__ float2 s_u[3][3][4];
    __shared__ float  s_qd[NWARP][DK];
    __shared__ float  s_kd[SEQ][DK];
    __shared__ float  s_ms[64];
    __shared__ int    s_finv[64];
    __shared__ float  s_mkT[DK][SEQ];
    __shared__ float2 s_phivT[DK][SEQ];
    __shared__ int    s_last;

    // ---- Phase 0: tables + stage x/W1 (coalesced float4) ----
    if (t < 64) {
        int y = permf(t);
        s_finv[y] = t;
        s_ms[t] = (__popc(y) & 1) ? -1.0f : 1.0f;
    }
    {
        const float4* xs = (const float4*)x;
        float4* xd = (float4*)pre_x;
        xd[t]       = xs[t];
        xd[t + 256] = xs[t + 256];
        if (t < 128) ((float4*)pre_w)[t] = ((const float4*)W1)[t];
    }
    // per-qubit 2x2 unitaries (needs only pqc)
    if (t >= 128 && t < 137) {
        int g = (t - 128) / 3, q = (t - 128) % 3;
        const float* ap = pqc + h * 27 + g * 9 + q * 3;
        float a0 = ap[0] * W_MUL, a1 = ap[1] * W_MUL, a2 = ap[2] * W_MUL;
        float sx, cx, sy, cy, sz, cz;
        sincosf(0.5f * a0, &sx, &cx);
        sincosf(0.5f * a1, &sy, &cy);
        sincosf(0.5f * a2, &sz, &cz);
        float2 m00 = make_float2(cy * cx,   sy * sx);
        float2 m01 = make_float2(-sy * cx, -cy * sx);
        float2 m10 = make_float2(sy * cx,  -cy * sx);
        float2 m11 = make_float2(cy * cx,  -sy * sx);
        float2 e0 = make_float2(cz, -sz);
        float2 e1 = make_float2(cz,  sz);
        s_u[g][q][0] = cmul(e0, m00);
        s_u[g][q][1] = cmul(e0, m01);
        s_u[g][q][2] = cmul(e1, m10);
        s_u[g][q][3] = cmul(e1, m11);
    }
    __syncthreads();

    // ---- Phase 1: xq = x @ W1^T + b1 (one output/thread) ----
    {
        int s = t >> 3, c = t & 7;
        float acc = b1[c];
#pragma unroll 16
        for (int d = 0; d < DM; d++)
            acc = fmaf(pre_x[s * DM + d], pre_w[c * DM + d], acc);
        s_xq[s][c] = acc;
    }
    __syncthreads();

    // ---- Phase 2: normalize ----
    {
        int s = t >> 3, c = t & 7;
        float n = 0.f;
#pragma unroll
        for (int e = 0; e < DK; e++) n = fmaf(s_xq[s][e], s_xq[s][e], n);
        s_psi[s][c] = s_xq[s][c] * rsqrtf(n);
    }
    __syncthreads();

    // ---- Phase 3: apply head unitaries ----
    {
        float2 v[8];
        if (t < 32) {                       // kd for s = t
            apply_u3(s_u[1], s_psi[t], v);
#pragma unroll
            for (int e = 0; e < 8; e++)
                s_kd[t][e] = fmaf(v[e].x, v[e].x, v[e].y * v[e].y);
        } else if (t < 64) {                // phiv (transposed) for s = t-32
            int s = t - 32;
            apply_u3(s_u[2], s_psi[s], v);
#pragma unroll
            for (int e = 0; e < 8; e++) s_phivT[e][s] = v[e];
        } else if (t < 64 + NWARP) {        // qd for chain t-64
            int ci = t - 64;
            apply_u3(s_u[0], s_psi[i0 + ci], v);
#pragma unroll
            for (int e = 0; e < 8; e++)
                s_qd[ci][e] = fmaf(v[e].x, v[e].x, v[e].y * v[e].y);
        }
    }
    __syncthreads();

    // ---- Phase 4: mkT[c][j] = sum_d ms[8c+d] kd[j][d] ----
    {
        int j = t >> 3, c = t & 7;
        float acc = 0.f;
#pragma unroll
        for (int d = 0; d < 8; d++)
            acc = fmaf(s_ms[c * 8 + d], s_kd[j][d], acc);
        s_mkT[c][j] = acc;
    }
    __syncthreads();

    // ---- Phase 5: per (chain=w, j=l): chi; W_j = chi chi^dagger ----
    {
        float acc = 0.f;
#pragma unroll
        for (int c = 0; c < 8; c++) acc = fmaf(s_qd[w][c], s_mkT[c][l], acc);
        float ph = acc * PI_F;
        float s4, c4, sh, ch;
        sincosf(0.25f * ph, &s4, &c4);
        sincosf(0.50f * ph, &sh, &ch);
        float cc2 = c4 * c4, ss2 = s4 * s4, cs2 = c4 * s4;
        float2 e0 = make_float2(ch, -sh);
        float2 e1 = make_float2(ch,  sh);
        float2 u0 = cmul(e0, make_float2(cc2,  ss2));
        float2 u1 = cmul(e0, make_float2(-cs2, -cs2));
        float2 u2 = cmul(e1, make_float2(cs2,  -cs2));
        float2 u3 = cmul(e1, make_float2(cc2,  -ss2));

        float2 v[8];
#pragma unroll
        for (int e = 0; e < 8; e++) v[e] = s_phivT[e][l];
#pragma unroll
        for (int q = 0; q < 3; q++) {
            int p = 2 - q;
#pragma unroll
            for (int k = 0; k < 8; k++) {
                if ((k >> p) & 1) continue;
                int k1 = k | (1 << p);
                float2 v0 = v[k], v1 = v[k1];
                v[k]  = cadd(cmul(u0, v0), cmul(u1, v1));
                v[k1] = cadd(cmul(u2, v0), cmul(u3, v1));
            }
        }
        float2* wrow = Wt + (w * SEQ + l) * WPAD;
#pragma unroll
        for (int y1 = 0; y1 < 8; y1++)
#pragma unroll
            for (int y2 = 0; y2 < 8; y2++)
                wrow[y1 * 8 + y2] = cmulc(v[y1], v[y2]);
    }

    // ---- Phase 6: per-lane gather constants ----
    const int a0 = l >> 3;
    const int c  = l & 7;
    int ro0[8], ro1[8], y0[8], y1[8];
#pragma unroll
    for (int b = 0; b < 8; b++) {
        int p0 = s_finv[a0 * 8 + b];
        int p1 = s_finv[(a0 + 4) * 8 + b];
        int pc = s_finv[c * 8 + b];
        ro0[b] = (p0 >> 3) * 8 + (pc >> 3);
        ro1[b] = (p1 >> 3) * 8 + (pc >> 3);
        y0[b]  = (p0 & 7) * 8 + (pc & 7);
        y1[b]  = (p1 & 7) * 8 + (pc & 7);
    }
    __syncwarp();   // warp-local W table ready

    // ---- Phase 7: scan (warp-synchronous); rho_0 = W_0 row ----
    float2* rw = rho + w * 128;
    rw[l]      = Wt[w * SEQ * WPAD + l];
    rw[l + 32] = Wt[w * SEQ * WPAD + l + 32];
    int cur = 0;
    __syncwarp();

    for (int j = 1; j < SEQ; j++) {
        const float2* rp = rw + cur * 64;
        const float2* wj = Wt + (w * SEQ + j) * WPAD;
        float2 acc0 = make_float2(0.f, 0.f);
        float2 acc1 = make_float2(0.f, 0.f);
#pragma unroll
        for (int b = 0; b < 8; b++) {
            cmac(acc0, rp[ro0[b]], wj[y0[b]]);
            cmac(acc1, rp[ro1[b]], wj[y1[b]]);
        }
        float2* rn = rw + (cur ^ 1) * 64;
        rn[l]      = acc0;
        rn[l + 32] = acc1;
        cur ^= 1;
        __syncwarp();
    }

    if (l < 8) {
        float2 v = rw[cur * 64 + l * 9];     // diagonal (l,l)
        int i = i0 + w;
        g_z[i * DM + h * DK + l] = v.x;
    }

    // ---- Phase 8: last block does the output projection ----
    __threadfence();
    __syncthreads();
    if (t == 0) s_last = (atomicAdd(&g_cnt, 1) == GRID - 1) ? 1 : 0;
    __syncthreads();
    if (!s_last) return;
    if (t == 0) g_cnt = 0;                  // reset for next graph replay
    __threadfence();

    // stage z (2048 floats) into shared (aliases dead W table)
#pragma unroll
    for (int k = 0; k < 8; k++) szf[t + 256 * k] = g_z[t + 256 * k];
    __syncthreads();

    {
        const int d   = t & 63;
        const int grp = t >> 6;              // 0..3 -> 8 sequences each
        float wreg[DM];
        {
            const float4* wr = (const float4*)(W2 + d * DM);
#pragma unroll
            for (int k = 0; k < 16; k++) {
                float4 v4 = wr[k];
                wreg[4 * k]     = v4.x;
                wreg[4 * k + 1] = v4.y;
                wreg[4 * k + 2] = v4.z;
                wreg[4 * k + 3] = v4.w;
            }
        }
        float bb = b2[d];
#pragma unroll
        for (int k = 0; k < 8; k++) {
            int s = grp * 8 + k;
            float acc = bb;
#pragma unroll
            for (int e = 0; e < DM; e++)
                acc = fmaf(szf[s * DM + e], wreg[e], acc);
            out[s * DM + d] = acc;
        }
    }
}

extern "C" void kernel_launch(void* const* d_in, const int* in_sizes, int n_in,
                              void* d_out, int out_size) {
    const float* x    = (const float*)d_in[0];
    const float* pqc  = (const float*)d_in[1];
    const float* W1   = (const float*)d_in[2];
    const float* b1   = (const float*)d_in[3];
    const float* W2   = (const float*)d_in[4];
    const float* b2   = (const float*)d_in[5];
    float* out = (float*)d_out;

    cudaFuncSetAttribute(qfused, cudaFuncAttributeMaxDynamicSharedMemorySize,
                         DYN_BYTES);
    qfused<<<GRID, 256, DYN_BYTES>>>(x, pqc, W1, b1, W2, b2, out);
}

// round 6
// speedup vs baseline: 1.4627x; 1.4627x over previous
#include <cuda_runtime.h>
#include <math.h>

#define NH 8
#define SEQ 32
#define DK 8
#define DM 64
#define PI_F 3.14159265358979323846f
#define W_MUL 0.6324555320336759f  // sqrt(2/5)

#define WPAD 65          // padded W-table row, in float2
#define GRID 128         // NH * 16 blocks, 64 threads, 2 chains each
#define XPAD 68          // padded x/W1 stage row (floats), float4-aligned

static __device__ float    g_z[SEQ * NH * DK];   // [s][h*8+e]
static __device__ unsigned g_cnt;                // zero-init; reset every run
static __device__ unsigned g_cnt2;               // tail cleanup counter

__device__ __forceinline__ float2 cmul(float2 a, float2 b) {
    return make_float2(fmaf(a.x, b.x, -a.y * b.y), fmaf(a.x, b.y, a.y * b.x));
}
// a * conj(b)
__device__ __forceinline__ float2 cmulc(float2 a, float2 b) {
    return make_float2(fmaf(a.x, b.x, a.y * b.y), fmaf(a.y, b.x, -a.x * b.y));
}
__device__ __forceinline__ float2 cadd(float2 a, float2 b) {
    return make_float2(a.x + b.x, a.y + b.y);
}
// acc += a * b (complex)
__device__ __forceinline__ void cmac(float2& acc, float2 a, float2 b) {
    acc.x = fmaf(a.x, b.x, fmaf(-a.y, b.y, acc.x));
    acc.y = fmaf(a.x, b.y, fmaf( a.y, b.x, acc.y));
}

// CNOT-ring basis permutation f(x)
__device__ __forceinline__ int permf(int x) {
#pragma unroll
    for (int t = 0; t < 6; t++) {
        int cb = 5 - t;
        int tb = 5 - ((t + 1) % 6);
        if ((x >> cb) & 1) x ^= (1 << tb);
    }
    return x;
}

// apply 3-qubit kron unitary (u[q][4], qubit 0 = MSB) to real vector psi[8]
__device__ __forceinline__ void apply_u3(const float2 (*u)[4], const float* psi,
                                         float2* v) {
#pragma unroll
    for (int e = 0; e < 8; e++) v[e] = make_float2(psi[e], 0.f);
#pragma unroll
    for (int q = 0; q < 3; q++) {
        int p = 2 - q;
        float2 u0 = u[q][0], u1 = u[q][1], u2 = u[q][2], u3 = u[q][3];
#pragma unroll
        for (int k = 0; k < 8; k++) {
            if ((k >> p) & 1) continue;
            int k1 = k | (1 << p);
            float2 v0 = v[k], v1 = v[k1];
            v[k]  = cadd(cmul(u0, v0), cmul(u1, v1));
            v[k1] = cadd(cmul(u2, v0), cmul(u3, v1));
        }
    }
}

// single kernel: grid=128, block=64; block b: head h = b>>4, chains (b&15)*2+{0,1}
__global__ void __launch_bounds__(64)
qfused(const float* __restrict__ x,     // (32,64)
       const float* __restrict__ pqc,   // (8,3,9)
       const float* __restrict__ W1,    // (8,64)
       const float* __restrict__ b1,    // (8,)
       const float* __restrict__ W2,    // (64,64)
       const float* __restrict__ b2,    // (64,)
       float* __restrict__ out)         // (1,32,64)
{
    const int h  = blockIdx.x >> 4;
    const int i0 = (blockIdx.x & 15) * 2;
    const int t  = threadIdx.x;      // 0..63
    const int w  = t >> 5;           // warp / chain index
    const int l  = t & 31;

    __shared__ union {
        struct { float x[SEQ][XPAD]; float W1[DK][XPAD]; } pre;  // 10.9 KB
        float2 W[2][SEQ][WPAD];                                  // 33.3 KB
        float  zs[8][DM];                                        // tail stage
    } ub;
    __shared__ float  s_xq [SEQ][9];
    __shared__ float  s_psi[SEQ][9];
    __shared__ float2 s_u[3][3][4];
    __shared__ float  s_qd[2][DK];
    __shared__ float  s_kd[SEQ][9];
    __shared__ float  s_ms[64];
    __shared__ int    s_finv[64];
    __shared__ float  s_mkT[DK][33];
    __shared__ float2 s_phivT[DK][SEQ];
    __shared__ float2 s_rho[2][2][64];
    __shared__ int    s_tail;

    // ---- Phase 0: tables + stage x/W1 (padded, coalesced float4) ----
    {
        int y = permf(t);
        s_finv[y] = t;
        s_ms[t] = (__popc(y) & 1) ? -1.0f : 1.0f;
    }
    {
        const float4* xs = (const float4*)x;
#pragma unroll
        for (int k = 0; k < 8; k++) {
            int q = t + 64 * k;           // 0..511
            int s = q >> 4, j = q & 15;
            *(float4*)&ub.pre.x[s][4 * j] = xs[q];
        }
        const float4* ws = (const float4*)W1;
#pragma unroll
        for (int k = 0; k < 2; k++) {
            int q = t + 64 * k;           // 0..127
            int c = q >> 4, j = q & 15;
            *(float4*)&ub.pre.W1[c][4 * j] = ws[q];
        }
    }
    if (t < 9) {
        int g = t / 3, q = t % 3;
        const float* ap = pqc + h * 27 + g * 9 + q * 3;
        float a0 = ap[0] * W_MUL, a1 = ap[1] * W_MUL, a2 = ap[2] * W_MUL;
        float sx, cx, sy, cy, sz, cz;
        sincosf(0.5f * a0, &sx, &cx);
        sincosf(0.5f * a1, &sy, &cy);
        sincosf(0.5f * a2, &sz, &cz);
        float2 m00 = make_float2(cy * cx,   sy * sx);
        float2 m01 = make_float2(-sy * cx, -cy * sx);
        float2 m10 = make_float2(sy * cx,  -cy * sx);
        float2 m11 = make_float2(cy * cx,  -sy * sx);
        float2 e0 = make_float2(cz, -sz);
        float2 e1 = make_float2(cz,  sz);
        s_u[g][q][0] = cmul(e0, m00);
        s_u[g][q][1] = cmul(e0, m01);
        s_u[g][q][2] = cmul(e1, m10);
        s_u[g][q][3] = cmul(e1, m11);
    }
    __syncthreads();

    // ---- Phase 1: xq = x @ W1^T + b1 (4 outputs/thread, shared c) ----
    {
        const int c  = t & 7;
        const int s0 = t >> 3;           // outputs s0, s0+8, s0+16, s0+24
        float a0 = b1[c], a1 = a0, a2 = a0, a3 = a0;
        const float4* wr  = (const float4*)&ub.pre.W1[c][0];
        const float4* xr0 = (const float4*)&ub.pre.x[s0][0];
        const float4* xr1 = (const float4*)&ub.pre.x[s0 + 8][0];
        const float4* xr2 = (const float4*)&ub.pre.x[s0 + 16][0];
        const float4* xr3 = (const float4*)&ub.pre.x[s0 + 24][0];
#pragma unroll
        for (int j = 0; j < 16; j++) {
            float4 wv = wr[j];
            float4 v0 = xr0[j], v1 = xr1[j], v2 = xr2[j], v3 = xr3[j];
            a0 = fmaf(v0.x, wv.x, fmaf(v0.y, wv.y, fmaf(v0.z, wv.z, fmaf(v0.w, wv.w, a0))));
            a1 = fmaf(v1.x, wv.x, fmaf(v1.y, wv.y, fmaf(v1.z, wv.z, fmaf(v1.w, wv.w, a1))));
            a2 = fmaf(v2.x, wv.x, fmaf(v2.y, wv.y, fmaf(v2.z, wv.z, fmaf(v2.w, wv.w, a2))));
            a3 = fmaf(v3.x, wv.x, fmaf(v3.y, wv.y, fmaf(v3.z, wv.z, fmaf(v3.w, wv.w, a3))));
        }
        s_xq[s0][c]      = a0;
        s_xq[s0 + 8][c]  = a1;
        s_xq[s0 + 16][c] = a2;
        s_xq[s0 + 24][c] = a3;
    }
    __syncthreads();

    // ---- Phase 2: normalize ----
#pragma unroll
    for (int k = 0; k < 4; k++) {
        int idx = t + 64 * k;
        int s = idx >> 3, c = idx & 7;
        float n = 0.f;
#pragma unroll
        for (int e = 0; e < DK; e++) n = fmaf(s_xq[s][e], s_xq[s][e], n);
        s_psi[s][c] = s_xq[s][c] * rsqrtf(n);
    }
    __syncthreads();

    // ---- Phase 3: apply head unitaries ----
    {
        float2 v[8];
        if (t < 32) {                       // kd for s = t
            apply_u3(s_u[1], s_psi[t], v);
#pragma unroll
            for (int e = 0; e < 8; e++)
                s_kd[t][e] = fmaf(v[e].x, v[e].x, v[e].y * v[e].y);
            if (t < 2) {                    // qd for chain t
                float2 vq[8];
                apply_u3(s_u[0], s_psi[i0 + t], vq);
#pragma unroll
                for (int e = 0; e < 8; e++)
                    s_qd[t][e] = fmaf(vq[e].x, vq[e].x, vq[e].y * vq[e].y);
            }
        } else {                            // phiv (transposed) for s = t-32
            int s = t - 32;
            apply_u3(s_u[2], s_psi[s], v);
#pragma unroll
            for (int e = 0; e < 8; e++) s_phivT[e][s] = v[e];
        }
    }
    __syncthreads();

    // ---- Phase 4: mkT[c][j] = sum_d ms[8c+d] kd[j][d] ----
#pragma unroll
    for (int k = 0; k < 4; k++) {
        int idx = t + 64 * k;
        int j = idx >> 3, c = idx & 7;
        float acc = 0.f;
#pragma unroll
        for (int d = 0; d < 8; d++)
            acc = fmaf(s_ms[c * 8 + d], s_kd[j][d], acc);
        s_mkT[c][j] = acc;
    }
    __syncthreads();

    // ---- Phase 5: per (chain=w, j=l): chi; W_j = chi chi^dagger ----
    {
        float acc = 0.f;
#pragma unroll
        for (int c = 0; c < 8; c++) acc = fmaf(s_qd[w][c], s_mkT[c][l], acc);
        float ph = acc * PI_F;
        float s4, c4, sh, ch;
        sincosf(0.25f * ph, &s4, &c4);
        sincosf(0.50f * ph, &sh, &ch);
        float cc2 = c4 * c4, ss2 = s4 * s4, cs2 = c4 * s4;
        float2 e0 = make_float2(ch, -sh);
        float2 e1 = make_float2(ch,  sh);
        float2 u0 = cmul(e0, make_float2(cc2,  ss2));
        float2 u1 = cmul(e0, make_float2(-cs2, -cs2));
        float2 u2 = cmul(e1, make_float2(cs2,  -cs2));
        float2 u3 = cmul(e1, make_float2(cc2,  -ss2));

        float2 v[8];
#pragma unroll
        for (int e = 0; e < 8; e++) v[e] = s_phivT[e][l];
#pragma unroll
        for (int q = 0; q < 3; q++) {
            int p = 2 - q;
#pragma unroll
            for (int k = 0; k < 8; k++) {
                if ((k >> p) & 1) continue;
                int k1 = k | (1 << p);
                float2 v0 = v[k], v1 = v[k1];
                v[k]  = cadd(cmul(u0, v0), cmul(u1, v1));
                v[k1] = cadd(cmul(u2, v0), cmul(u3, v1));
            }
        }
        float2* wrow = &ub.W[w][l][0];
#pragma unroll
        for (int y1 = 0; y1 < 8; y1++)
#pragma unroll
            for (int y2 = 0; y2 < 8; y2++)
                wrow[y1 * 8 + y2] = cmulc(v[y1], v[y2]);
    }

    // ---- Phase 6: per-lane gather constants ----
    const int a0i = l >> 3;
    const int ci  = l & 7;
    int ro0[8], ro1[8], y0[8], y1[8];
#pragma unroll
    for (int b = 0; b < 8; b++) {
        int p0 = s_finv[a0i * 8 + b];
        int p1 = s_finv[(a0i + 4) * 8 + b];
        int pc = s_finv[ci * 8 + b];
        ro0[b] = (p0 >> 3) * 8 + (pc >> 3);
        ro1[b] = (p1 >> 3) * 8 + (pc >> 3);
        y0[b]  = (p0 & 7) * 8 + (pc & 7);
        y1[b]  = (p1 & 7) * 8 + (pc & 7);
    }
    __syncwarp();   // warp-local W table ready

    // ---- Phase 7: scan; rho_0 = W_0 row; split accumulators ----
    s_rho[w][0][l]      = ub.W[w][0][l];
    s_rho[w][0][l + 32] = ub.W[w][0][l + 32];
    int cur = 0;
    __syncwarp();

    for (int j = 1; j < SEQ; j++) {
        const float2* rp = s_rho[w][cur];
        const float2* wj = &ub.W[w][j][0];
        float2 a0a = make_float2(0.f, 0.f), a0b = make_float2(0.f, 0.f);
        float2 a1a = make_float2(0.f, 0.f), a1b = make_float2(0.f, 0.f);
#pragma unroll
        for (int b = 0; b < 4; b++) {
            cmac(a0a, rp[ro0[b]],     wj[y0[b]]);
            cmac(a0b, rp[ro0[b + 4]], wj[y0[b + 4]]);
            cmac(a1a, rp[ro1[b]],     wj[y1[b]]);
            cmac(a1b, rp[ro1[b + 4]], wj[y1[b + 4]]);
        }
        s_rho[w][cur ^ 1][l]      = cadd(a0a, a0b);
        s_rho[w][cur ^ 1][l + 32] = cadd(a1a, a1b);
        cur ^= 1;
        __syncwarp();
    }

    if (l < 8) {
        float2 v = s_rho[w][cur][l * 9];     // diagonal (l,l)
        int i = i0 + w;
        g_z[i * DM + h * DK + l] = v.x;
    }

    // ---- Phase 8: ticket; last 4 blocks do the output projection ----
    __threadfence();
    __syncthreads();
    if (t == 0) {
        unsigned tk = atomicAdd(&g_cnt, 1u);
        s_tail = (tk >= GRID - 4) ? (int)(tk - (GRID - 4)) : -1;
    }
    __syncthreads();
    const int tail = s_tail;
    if (tail < 0) return;

    // wait until all 128 blocks have published z
    if (t == 0) {
        while (atomicAdd(&g_cnt, 0u) < GRID) { }
    }
    __syncthreads();
    __threadfence();

    const int sbase = tail * 8;              // this block's 8 sequences
    // stage z rows (bypass L1: written by other SMs)
#pragma unroll
    for (int k = 0; k < 8; k++)
        (&ub.zs[0][0])[t + 64 * k] = __ldcg(&g_z[sbase * DM + t + 64 * k]);
    __syncthreads();

    {
        const int d = t;                     // output column
        float wreg[DM];
        const float4* wr = (const float4*)(W2 + d * DM);
#pragma unroll
        for (int k = 0; k < 16; k++) {
            float4 v4 = wr[k];
            wreg[4 * k]     = v4.x;
            wreg[4 * k + 1] = v4.y;
            wreg[4 * k + 2] = v4.z;
            wreg[4 * k + 3] = v4.w;
        }
        float bb = b2[d];
#pragma unroll
        for (int k = 0; k < 8; k++) {
            float acc = bb;
#pragma unroll
            for (int e = 0; e < DM; e++)
                acc = fmaf(ub.zs[k][e], wreg[e], acc);
            out[(sbase + k) * DM + d] = acc;
        }
    }

    // cleanup: last tail block resets counters for the next graph replay
    __syncthreads();
    if (t == 0) {
        unsigned t2 = atomicAdd(&g_cnt2, 1u);
        if (t2 == 3u) {
            g_cnt  = 0u;
            g_cnt2 = 0u;
            __threadfence();
        }
    }
}

extern "C" void kernel_launch(void* const* d_in, const int* in_sizes, int n_in,
                              void* d_out, int out_size) {
    const float* x    = (const float*)d_in[0];
    const float* pqc  = (const float*)d_in[1];
    const float* W1   = (const float*)d_in[2];
    const float* b1   = (const float*)d_in[3];
    const float* W2   = (const float*)d_in[4];
    const float* b2   = (const float*)d_in[5];
    float* out = (float*)d_out;

    qfused<<<GRID, 64>>>(x, pqc, W1, b1, W2, b2, out);
}

// round 7
// speedup vs baseline: 1.6645x; 1.1380x over previous
#include <cuda_runtime.h>
#include <math.h>

#define NH 8
#define SEQ 32
#define DK 8
#define DM 64
#define PI_F 3.14159265358979323846f
#define W_MUL 0.6324555320336759f  // sqrt(2/5)

#define GRID 128         // NH*16 blocks, 64 threads, 2 chains each
#define XPAD 68          // padded x/W1 stage row (floats)
#define NTAIL 8          // tail blocks doing the output GEMV

static __device__ float    g_z[SEQ * NH * DK];   // [s][h*8+e]
static __device__ unsigned g_cnt;                // zero-init; reset every run
static __device__ unsigned g_cnt2;               // tail cleanup counter

__device__ __forceinline__ float2 cmul(float2 a, float2 b) {
    return make_float2(fmaf(a.x, b.x, -a.y * b.y), fmaf(a.x, b.y, a.y * b.x));
}
// a * conj(b)
__device__ __forceinline__ float2 cmulc(float2 a, float2 b) {
    return make_float2(fmaf(a.x, b.x, a.y * b.y), fmaf(a.y, b.x, -a.x * b.y));
}
__device__ __forceinline__ float2 cadd(float2 a, float2 b) {
    return make_float2(a.x + b.x, a.y + b.y);
}
// acc += a*b
__device__ __forceinline__ void cmac(float2& acc, float2 a, float2 b) {
    acc.x = fmaf(a.x, b.x, fmaf(-a.y, b.y, acc.x));
    acc.y = fmaf(a.x, b.y, fmaf( a.y, b.x, acc.y));
}

// CNOT-ring basis permutation f(x) (for the ms sign table only)
__device__ __forceinline__ int permf(int x) {
#pragma unroll
    for (int t = 0; t < 6; t++) {
        int cb = 5 - t;
        int tb = 5 - ((t + 1) % 6);
        if ((x >> cb) & 1) x ^= (1 << tb);
    }
    return x;
}

// flat-64 gather permutation: P(m) = r(m>>3)*8 + r(m&7), r(a) = a ^ (a>>1). order 4.
__device__ __forceinline__ int Pmap(int m) {
    int a = m >> 3, c = m & 7;
    int ra = (a ^ (a >> 1)) & 7;
    int rc = (c ^ (c >> 1)) & 7;
    return ra * 8 + rc;
}

__device__ __forceinline__ void apply_u3(const float2 (*u)[4], const float* psi,
                                         float2* v) {
#pragma unroll
    for (int e = 0; e < 8; e++) v[e] = make_float2(psi[e], 0.f);
#pragma unroll
    for (int q = 0; q < 3; q++) {
        int p = 2 - q;
        float2 u0 = u[q][0], u1 = u[q][1], u2 = u[q][2], u3 = u[q][3];
#pragma unroll
        for (int k = 0; k < 8; k++) {
            if ((k >> p) & 1) continue;
            int k1 = k | (1 << p);
            float2 v0 = v[k], v1 = v[k1];
            v[k]  = cadd(cmul(u0, v0), cmul(u1, v1));
            v[k1] = cadd(cmul(u2, v0), cmul(u3, v1));
        }
    }
}

__device__ __forceinline__ float2 shfl2(float2 v, int m) {
    return make_float2(__shfl_xor_sync(0xffffffffu, v.x, m),
                       __shfl_xor_sync(0xffffffffu, v.y, m));
}

// single kernel: grid=128, block=64; block b: head h=b>>4, chains (b&15)*2+{0,1}
__global__ void __launch_bounds__(64)
qfused(const float* __restrict__ x,     // (32,64)
       const float* __restrict__ pqc,   // (8,3,9)
       const float* __restrict__ W1,    // (8,64)
       const float* __restrict__ b1,    // (8,)
       const float* __restrict__ W2,    // (64,64)
       const float* __restrict__ b2,    // (64,)
       float* __restrict__ out)         // (1,32,64)
{
    const int h  = blockIdx.x >> 4;
    const int i0 = (blockIdx.x & 15) * 2;
    const int t  = threadIdx.x;      // 0..63
    const int w  = t >> 5;           // warp / chain index
    const int l  = t & 31;

    __shared__ union {
        struct { float x[SEQ][XPAD]; float W1[DK][XPAD]; } pre;  // 10.9 KB
        float zs[4][DM];                                         // tail stage
    } ub;
    __shared__ float  s_xq [SEQ][9];
    __shared__ float  s_psi[SEQ][9];
    __shared__ float2 s_u[3][3][4];
    __shared__ float  s_qd[2][DK];
    __shared__ float  s_kd[SEQ][9];
    __shared__ float  s_ms[64];
    __shared__ float  s_mkT[DK][33];
    __shared__ float2 s_phivT[DK][SEQ];
    __shared__ float4 s_V4[2][SEQ][2];   // per (warp, j): {V00,V01},{V10,V11}
    __shared__ float2 s_chi0[2][8];
    __shared__ float  s_fin[2][64];
    __shared__ int    s_tail;

    // ---- Phase 0: sign table + stage x/W1 ----
    s_ms[t] = (__popc(permf(t)) & 1) ? -1.0f : 1.0f;
    {
        const float4* xs = (const float4*)x;
#pragma unroll
        for (int k = 0; k < 8; k++) {
            int q = t + 64 * k;
            int s = q >> 4, j = q & 15;
            *(float4*)&ub.pre.x[s][4 * j] = xs[q];
        }
        const float4* ws = (const float4*)W1;
#pragma unroll
        for (int k = 0; k < 2; k++) {
            int q = t + 64 * k;
            int c = q >> 4, j = q & 15;
            *(float4*)&ub.pre.W1[c][4 * j] = ws[q];
        }
    }
    if (t < 9) {
        int g = t / 3, q = t % 3;
        const float* ap = pqc + h * 27 + g * 9 + q * 3;
        float a0 = ap[0] * W_MUL, a1 = ap[1] * W_MUL, a2 = ap[2] * W_MUL;
        float sx, cx, sy, cy, sz, cz;
        __sincosf(0.5f * a0, &sx, &cx);
        __sincosf(0.5f * a1, &sy, &cy);
        __sincosf(0.5f * a2, &sz, &cz);
        float2 m00 = make_float2(cy * cx,   sy * sx);
        float2 m01 = make_float2(-sy * cx, -cy * sx);
        float2 m10 = make_float2(sy * cx,  -cy * sx);
        float2 m11 = make_float2(cy * cx,  -sy * sx);
        float2 e0 = make_float2(cz, -sz);
        float2 e1 = make_float2(cz,  sz);
        s_u[g][q][0] = cmul(e0, m00);
        s_u[g][q][1] = cmul(e0, m01);
        s_u[g][q][2] = cmul(e1, m10);
        s_u[g][q][3] = cmul(e1, m11);
    }
    __syncthreads();

    // ---- Phase 1: xq = x @ W1^T + b1 (4 outputs/thread, shared W1 row) ----
    {
        const int c  = t & 7;
        const int s0 = t >> 3;
        float a0 = b1[c], a1 = a0, a2 = a0, a3 = a0;
        const float4* wr  = (const float4*)&ub.pre.W1[c][0];
        const float4* xr0 = (const float4*)&ub.pre.x[s0][0];
        const float4* xr1 = (const float4*)&ub.pre.x[s0 + 8][0];
        const float4* xr2 = (const float4*)&ub.pre.x[s0 + 16][0];
        const float4* xr3 = (const float4*)&ub.pre.x[s0 + 24][0];
#pragma unroll
        for (int j = 0; j < 16; j++) {
            float4 wv = wr[j];
            float4 v0 = xr0[j], v1 = xr1[j], v2 = xr2[j], v3 = xr3[j];
            a0 = fmaf(v0.x, wv.x, fmaf(v0.y, wv.y, fmaf(v0.z, wv.z, fmaf(v0.w, wv.w, a0))));
            a1 = fmaf(v1.x, wv.x, fmaf(v1.y, wv.y, fmaf(v1.z, wv.z, fmaf(v1.w, wv.w, a1))));
            a2 = fmaf(v2.x, wv.x, fmaf(v2.y, wv.y, fmaf(v2.z, wv.z, fmaf(v2.w, wv.w, a2))));
            a3 = fmaf(v3.x, wv.x, fmaf(v3.y, wv.y, fmaf(v3.z, wv.z, fmaf(v3.w, wv.w, a3))));
        }
        s_xq[s0][c]      = a0;
        s_xq[s0 + 8][c]  = a1;
        s_xq[s0 + 16][c] = a2;
        s_xq[s0 + 24][c] = a3;
    }
    __syncthreads();

    // ---- Phase 2: normalize ----
#pragma unroll
    for (int k = 0; k < 4; k++) {
        int idx = t + 64 * k;
        int s = idx >> 3, c = idx & 7;
        float n = 0.f;
#pragma unroll
        for (int e = 0; e < DK; e++) n = fmaf(s_xq[s][e], s_xq[s][e], n);
        s_psi[s][c] = s_xq[s][c] * rsqrtf(n);
    }
    __syncthreads();

    // ---- Phase 3: apply head unitaries ----
    {
        float2 v[8];
        if (t < 32) {                       // kd for s = t
            apply_u3(s_u[1], s_psi[t], v);
#pragma unroll
            for (int e = 0; e < 8; e++)
                s_kd[t][e] = fmaf(v[e].x, v[e].x, v[e].y * v[e].y);
            if (t < 2) {                    // qd for chain t
                float2 vq[8];
                apply_u3(s_u[0], s_psi[i0 + t], vq);
#pragma unroll
                for (int e = 0; e < 8; e++)
                    s_qd[t][e] = fmaf(vq[e].x, vq[e].x, vq[e].y * vq[e].y);
            }
        } else {                            // phiv (transposed) for s = t-32
            int s = t - 32;
            apply_u3(s_u[2], s_psi[s], v);
#pragma unroll
            for (int e = 0; e < 8; e++) s_phivT[e][s] = v[e];
        }
    }
    __syncthreads();

    // ---- Phase 4: mkT[c][j] = sum_d ms[8c+d] kd[j][d] ----
#pragma unroll
    for (int k = 0; k < 4; k++) {
        int idx = t + 64 * k;
        int j = idx >> 3, c = idx & 7;
        float acc = 0.f;
#pragma unroll
        for (int d = 0; d < 8; d++)
            acc = fmaf(s_ms[c * 8 + d], s_kd[j][d], acc);
        s_mkT[c][j] = acc;
    }
    __syncthreads();

    // ---- Phase 5: per (chain=w, j=l): chi_j, then V row (4 complex) ----
    {
        float acc = 0.f;
#pragma unroll
        for (int c = 0; c < 8; c++) acc = fmaf(s_qd[w][c], s_mkT[c][l], acc);
        float ph = acc * PI_F;
        float s4, c4, sh, ch;
        __sincosf(0.25f * ph, &s4, &c4);
        __sincosf(0.50f * ph, &sh, &ch);
        float cc2 = c4 * c4, ss2 = s4 * s4, cs2 = c4 * s4;
        float2 e0 = make_float2(ch, -sh);
        float2 e1 = make_float2(ch,  sh);
        float2 u0 = cmul(e0, make_float2(cc2,  ss2));
        float2 u1 = cmul(e0, make_float2(-cs2, -cs2));
        float2 u2 = cmul(e1, make_float2(cs2,  -cs2));
        float2 u3 = cmul(e1, make_float2(cc2,  -ss2));

        float2 v[8];
#pragma unroll
        for (int e = 0; e < 8; e++) v[e] = s_phivT[e][l];
#pragma unroll
        for (int q = 0; q < 3; q++) {
            int p = 2 - q;
#pragma unroll
            for (int k = 0; k < 8; k++) {
                if ((k >> p) & 1) continue;
                int k1 = k | (1 << p);
                float2 v0 = v[k], v1 = v[k1];
                v[k]  = cadd(cmul(u0, v0), cmul(u1, v1));
                v[k1] = cadd(cmul(u2, v0), cmul(u3, v1));
            }
        }
        // V(p,g) = sum over parity-p rows y of chi[y]*conj(chi[y^4g])
        float n0 = fmaf(v[0].x, v[0].x, v[0].y * v[0].y)
                 + fmaf(v[3].x, v[3].x, v[3].y * v[3].y)
                 + fmaf(v[5].x, v[5].x, v[5].y * v[5].y)
                 + fmaf(v[6].x, v[6].x, v[6].y * v[6].y);
        float n1 = fmaf(v[1].x, v[1].x, v[1].y * v[1].y)
                 + fmaf(v[2].x, v[2].x, v[2].y * v[2].y)
                 + fmaf(v[4].x, v[4].x, v[4].y * v[4].y)
                 + fmaf(v[7].x, v[7].x, v[7].y * v[7].y);
        float2 V01 = make_float2(0.f, 0.f), V11 = make_float2(0.f, 0.f);
        V01 = cadd(V01, cmulc(v[0], v[4]));
        V01 = cadd(V01, cmulc(v[3], v[7]));
        V01 = cadd(V01, cmulc(v[5], v[1]));
        V01 = cadd(V01, cmulc(v[6], v[2]));
        V11 = cadd(V11, cmulc(v[1], v[5]));
        V11 = cadd(V11, cmulc(v[2], v[6]));
        V11 = cadd(V11, cmulc(v[4], v[0]));
        V11 = cadd(V11, cmulc(v[7], v[3]));
        s_V4[w][l][0] = make_float4(n0, 0.f, V01.x, V01.y);
        s_V4[w][l][1] = make_float4(n1, 0.f, V11.x, V11.y);
        if (l == 0) {
#pragma unroll
            for (int e = 0; e < 8; e++) s_chi0[w][e] = v[e];
        }
    }
    __syncwarp();

    // ---- Phase 6: drifting-coordinate register scan ----
    // stored_j[m] = rho_j[P^{-j}(m)]; lane l holds m=l (r0) and m=l+32 (r1).
    // per-slot, per-(j mod 4) selector: sel = a0*2 + g of u = P^{-j}(m)
    int selA0[4], selA1[4];
    {
        int m = l;
        int p1 = Pmap(m), p2 = Pmap(p1), p3 = Pmap(p2);
        selA0[0] = (((m  >> 3) & 1) << 1) | ((((m  >> 3) ^ m ) & 1));
        selA0[1] = (((p3 >> 3) & 1) << 1) | ((((p3 >> 3) ^ p3) & 1));
        selA0[2] = (((p2 >> 3) & 1) << 1) | ((((p2 >> 3) ^ p2) & 1));
        selA0[3] = (((p1 >> 3) & 1) << 1) | ((((p1 >> 3) ^ p1) & 1));
        m = l + 32;
        p1 = Pmap(m); p2 = Pmap(p1); p3 = Pmap(p2);
        selA1[0] = (((m  >> 3) & 1) << 1) | ((((m  >> 3) ^ m ) & 1));
        selA1[1] = (((p3 >> 3) & 1) << 1) | ((((p3 >> 3) ^ p3) & 1));
        selA1[2] = (((p2 >> 3) & 1) << 1) | ((((p2 >> 3) ^ p2) & 1));
        selA1[3] = (((p1 >> 3) & 1) << 1) | ((((p1 >> 3) ^ p1) & 1));
    }
    const int dmarr[4] = {4, 22, 13, 31};   // lane-xor mask of delta_j, idx j&3

    // init: stored_0 = rho_0 = chi_0 chi_0^dagger
    float2 r0, r1;
    {
        float2 ca  = s_chi0[w][l >> 3];
        float2 ca1 = s_chi0[w][4 + (l >> 3)];
        float2 cc  = s_chi0[w][l & 7];
        r0 = cmulc(ca, cc);
        r1 = cmulc(ca1, cc);
    }

#pragma unroll
    for (int j = 1; j < SEQ; j++) {
        const int k  = j & 3;
        const int dm = dmarr[k];
        float4 va = s_V4[w][j][0];
        float4 vb = s_V4[w][j][1];
        float2 v00 = make_float2(va.x, va.y), v01 = make_float2(va.z, va.w);
        float2 v10 = make_float2(vb.x, vb.y), v11 = make_float2(vb.z, vb.w);

        float2 p0 = shfl2(r1, dm);   // partner of slot0 lives in slot1
        float2 p1 = shfl2(r0, dm);

        int s0 = selA0[k];
        float2 g0a = (s0 & 1) ? v01 : v00;
        float2 g0b = (s0 & 1) ? v11 : v10;
        float2 VA0 = (s0 & 2) ? g0b : g0a;
        float2 VB0 = (s0 & 2) ? g0a : g0b;
        int s1 = selA1[k];
        float2 g1a = (s1 & 1) ? v01 : v00;
        float2 g1b = (s1 & 1) ? v11 : v10;
        float2 VA1 = (s1 & 2) ? g1b : g1a;
        float2 VB1 = (s1 & 2) ? g1a : g1b;

        float2 n0 = cmul(r0, VA0); cmac(n0, p0, VB0);
        float2 n1 = cmul(r1, VA1); cmac(n1, p1, VB1);
        r0 = n0; r1 = n1;
    }

    // undrift + diagonal: rho_31[u] = stored_31[P^3(u)] (31 mod 4 == 3)
    s_fin[w][l]      = r0.x;
    s_fin[w][l + 32] = r1.x;
    __syncwarp();
    if (l < 8) {
        int mm = Pmap(Pmap(Pmap(l * 9)));
        int i = i0 + w;
        g_z[i * DM + h * DK + l] = s_fin[w][mm];
    }

    // ---- Phase 7: ticket; last NTAIL blocks do the output projection ----
    __threadfence();
    __syncthreads();
    if (t == 0) {
        unsigned tk = atomicAdd(&g_cnt, 1u);
        s_tail = (tk >= GRID - NTAIL) ? (int)(tk - (GRID - NTAIL)) : -1;
    }
    __syncthreads();
    const int tail = s_tail;
    if (tail < 0) return;

    if (t == 0) {
        while (atomicAdd(&g_cnt, 0u) < GRID) { }
    }
    __syncthreads();
    __threadfence();

    const int sbase = tail * 4;             // this block's 4 sequences
#pragma unroll
    for (int k = 0; k < 4; k++)
        (&ub.zs[0][0])[t + 64 * k] = __ldcg(&g_z[sbase * DM + t + 64 * k]);
    __syncthreads();

    {
        const int d = t;                    // output column
        float wreg[DM];
        const float4* wr = (const float4*)(W2 + d * DM);
#pragma unroll
        for (int k = 0; k < 16; k++) {
            float4 v4 = wr[k];
            wreg[4 * k]     = v4.x;
            wreg[4 * k + 1] = v4.y;
            wreg[4 * k + 2] = v4.z;
            wreg[4 * k + 3] = v4.w;
        }
        float bb = b2[d];
#pragma unroll
        for (int k = 0; k < 4; k++) {
            float acc = bb;
#pragma unroll
            for (int e = 0; e < DM; e++)
                acc = fmaf(ub.zs[k][e], wreg[e], acc);
            out[(sbase + k) * DM + d] = acc;
        }
    }

    __syncthreads();
    if (t == 0) {
        unsigned t2 = atomicAdd(&g_cnt2, 1u);
        if (t2 == NTAIL - 1u) {
            g_cnt  = 0u;
            g_cnt2 = 0u;
            __threadfence();
        }
    }
}

extern "C" void kernel_launch(void* const* d_in, const int* in_sizes, int n_in,
                              void* d_out, int out_size) {
    const float* x    = (const float*)d_in[0];
    const float* pqc  = (const float*)d_in[1];
    const float* W1   = (const float*)d_in[2];
    const float* b1   = (const float*)d_in[3];
    const float* W2   = (const float*)d_in[4];
    const float* b2   = (const float*)d_in[5];
    float* out = (float*)d_out;

    qfused<<<GRID, 64>>>(x, pqc, W1, b1, W2, b2, out);
}

// round 8
// speedup vs baseline: 1.9216x; 1.1544x over previous
#include <cuda_runtime.h>
#include <math.h>

#define NH 8
#define SEQ 32
#define DK 8
#define DM 64
#define PI_F 3.14159265358979323846f
#define W_MUL 0.6324555320336759f  // sqrt(2/5)

#define GRID 64          // NH * 8 blocks; 128 threads; 4 chains/block
#define XPAD 68          // padded x/W1 stage row (floats)

static __device__ unsigned g_flag[SEQ];   // per-row "initialized" flag
static __device__ unsigned g_done[SEQ];   // per-row adder count

__device__ __forceinline__ float2 cmul(float2 a, float2 b) {
    return make_float2(fmaf(a.x, b.x, -a.y * b.y), fmaf(a.x, b.y, a.y * b.x));
}
// a * conj(b)
__device__ __forceinline__ float2 cmulc(float2 a, float2 b) {
    return make_float2(fmaf(a.x, b.x, a.y * b.y), fmaf(a.y, b.x, -a.x * b.y));
}
__device__ __forceinline__ float2 cadd(float2 a, float2 b) {
    return make_float2(a.x + b.x, a.y + b.y);
}
// acc += a*b
__device__ __forceinline__ void cmac(float2& acc, float2 a, float2 b) {
    acc.x = fmaf(a.x, b.x, fmaf(-a.y, b.y, acc.x));
    acc.y = fmaf(a.x, b.y, fmaf( a.y, b.x, acc.y));
}

// CNOT-ring basis permutation f(x) (sign table only)
__device__ __forceinline__ int permf(int x) {
#pragma unroll
    for (int t = 0; t < 6; t++) {
        int cb = 5 - t;
        int tb = 5 - ((t + 1) % 6);
        if ((x >> cb) & 1) x ^= (1 << tb);
    }
    return x;
}

// flat-64 gather permutation: P(m) = r(m>>3)*8 + r(m&7), r(a)=a^(a>>1). order 4.
__device__ __forceinline__ int Pmap(int m) {
    int a = m >> 3, c = m & 7;
    int ra = (a ^ (a >> 1)) & 7;
    int rc = (c ^ (c >> 1)) & 7;
    return ra * 8 + rc;
}

__device__ __forceinline__ void apply_u3(const float2 (*u)[4], const float* psi,
                                         float2* v) {
#pragma unroll
    for (int e = 0; e < 8; e++) v[e] = make_float2(psi[e], 0.f);
#pragma unroll
    for (int q = 0; q < 3; q++) {
        int p = 2 - q;
        float2 u0 = u[q][0], u1 = u[q][1], u2 = u[q][2], u3 = u[q][3];
#pragma unroll
        for (int k = 0; k < 8; k++) {
            if ((k >> p) & 1) continue;
            int k1 = k | (1 << p);
            float2 v0 = v[k], v1 = v[k1];
            v[k]  = cadd(cmul(u0, v0), cmul(u1, v1));
            v[k1] = cadd(cmul(u2, v0), cmul(u3, v1));
        }
    }
}

__device__ __forceinline__ float2 shfl2(float2 v, int m) {
    return make_float2(__shfl_xor_sync(0xffffffffu, v.x, m),
                       __shfl_xor_sync(0xffffffffu, v.y, m));
}

// grid=64, block=128; block b: head h=b>>3, group g=b&7, chains i = g*4 + w
__global__ void __launch_bounds__(128)
qfused(const float* __restrict__ x,     // (32,64)
       const float* __restrict__ pqc,   // (8,3,9)
       const float* __restrict__ W1,    // (8,64)
       const float* __restrict__ b1,    // (8,)
       const float* __restrict__ W2,    // (64,64)
       const float* __restrict__ b2,    // (64,)
       float* __restrict__ out)         // (1,32,64)
{
    const int h  = blockIdx.x >> 3;
    const int gg = blockIdx.x & 7;
    const int i0 = gg * 4;
    const int t  = threadIdx.x;      // 0..127
    const int w  = t >> 5;           // warp = chain index 0..3
    const int l  = t & 31;

    __shared__ float  s_xs [SEQ][XPAD];    // staged x
    __shared__ float  s_ws [DK][XPAD];     // staged W1
    __shared__ float  s_xq [SEQ][9];
    __shared__ float  s_psi[SEQ][9];
    __shared__ float2 s_u[3][3][4];
    __shared__ float  s_qd[4][DK];
    __shared__ float  s_kd[SEQ][9];
    __shared__ float  s_ms[64];
    __shared__ float  s_mkT[DK][33];
    __shared__ float2 s_phivT[DK][SEQ];
    __shared__ float4 s_V4[4][SEQ][2];     // per (warp,j): {V00,V01},{V10,V11}
    __shared__ float2 s_chi0[4][8];
    __shared__ float  s_fin[4][64];
    __shared__ float  s_z[4][8];

    // ---- Phase 0: sign table + stage x/W1 + unitaries ----
    if (t < 64) s_ms[t] = (__popc(permf(t)) & 1) ? -1.0f : 1.0f;
    {
        const float4* xs = (const float4*)x;
#pragma unroll
        for (int k = 0; k < 4; k++) {
            int q = t + 128 * k;          // 0..511
            int s = q >> 4, j = q & 15;
            *(float4*)&s_xs[s][4 * j] = xs[q];
        }
        const float4* ws = (const float4*)W1;
        {
            int q = t & 127;              // 0..127
            int c = q >> 4, j = q & 15;
            *(float4*)&s_ws[c][4 * j] = ws[q];
        }
    }
    if (t >= 64 && t < 73) {
        int tt = t - 64;
        int g = tt / 3, q = tt % 3;
        const float* ap = pqc + h * 27 + g * 9 + q * 3;
        float a0 = ap[0] * W_MUL, a1 = ap[1] * W_MUL, a2 = ap[2] * W_MUL;
        float sx, cx, sy, cy, sz, cz;
        __sincosf(0.5f * a0, &sx, &cx);
        __sincosf(0.5f * a1, &sy, &cy);
        __sincosf(0.5f * a2, &sz, &cz);
        float2 m00 = make_float2(cy * cx,   sy * sx);
        float2 m01 = make_float2(-sy * cx, -cy * sx);
        float2 m10 = make_float2(sy * cx,  -cy * sx);
        float2 m11 = make_float2(cy * cx,  -sy * sx);
        float2 e0 = make_float2(cz, -sz);
        float2 e1 = make_float2(cz,  sz);
        s_u[g][q][0] = cmul(e0, m00);
        s_u[g][q][1] = cmul(e0, m01);
        s_u[g][q][2] = cmul(e1, m10);
        s_u[g][q][3] = cmul(e1, m11);
    }
    __syncthreads();

    // ---- Phase 1: xq = x @ W1^T + b1 (2 outputs/thread) ----
    {
        const int c  = t & 7;
        const int s0 = t >> 3;            // 0..15; outputs s0, s0+16
        float a0 = b1[c], a1 = a0;
        const float4* wr  = (const float4*)&s_ws[c][0];
        const float4* xr0 = (const float4*)&s_xs[s0][0];
        const float4* xr1 = (const float4*)&s_xs[s0 + 16][0];
#pragma unroll
        for (int j = 0; j < 16; j++) {
            float4 wv = wr[j];
            float4 v0 = xr0[j], v1 = xr1[j];
            a0 = fmaf(v0.x, wv.x, fmaf(v0.y, wv.y, fmaf(v0.z, wv.z, fmaf(v0.w, wv.w, a0))));
            a1 = fmaf(v1.x, wv.x, fmaf(v1.y, wv.y, fmaf(v1.z, wv.z, fmaf(v1.w, wv.w, a1))));
        }
        s_xq[s0][c]      = a0;
        s_xq[s0 + 16][c] = a1;
    }
    __syncthreads();

    // ---- Phase 2: normalize (2 outputs/thread) ----
#pragma unroll
    for (int k = 0; k < 2; k++) {
        int idx = t + 128 * k;
        int s = idx >> 3, c = idx & 7;
        float n = 0.f;
#pragma unroll
        for (int e = 0; e < DK; e++) n = fmaf(s_xq[s][e], s_xq[s][e], n);
        s_psi[s][c] = s_xq[s][c] * rsqrtf(n);
    }
    __syncthreads();

    // ---- Phase 3: apply head unitaries (1 unit/thread) ----
    {
        float2 v[8];
        if (t < 32) {                       // kd for s = t
            apply_u3(s_u[1], s_psi[t], v);
#pragma unroll
            for (int e = 0; e < 8; e++)
                s_kd[t][e] = fmaf(v[e].x, v[e].x, v[e].y * v[e].y);
        } else if (t < 64) {                // phiv (transposed) for s = t-32
            int s = t - 32;
            apply_u3(s_u[2], s_psi[s], v);
#pragma unroll
            for (int e = 0; e < 8; e++) s_phivT[e][s] = v[e];
        } else if (t < 68) {                // qd for chain t-64
            int ci = t - 64;
            apply_u3(s_u[0], s_psi[i0 + ci], v);
#pragma unroll
            for (int e = 0; e < 8; e++)
                s_qd[ci][e] = fmaf(v[e].x, v[e].x, v[e].y * v[e].y);
        }
    }
    __syncthreads();

    // ---- Phase 4: mkT[c][j] = sum_d ms[8c+d] kd[j][d] (2/thread) ----
#pragma unroll
    for (int k = 0; k < 2; k++) {
        int idx = t + 128 * k;
        int j = idx >> 3, c = idx & 7;
        float acc = 0.f;
#pragma unroll
        for (int d = 0; d < 8; d++)
            acc = fmaf(s_ms[c * 8 + d], s_kd[j][d], acc);
        s_mkT[c][j] = acc;
    }
    __syncthreads();

    // ---- Phase 5: per (chain=w, j=l): chi_j, V row ----
    {
        float acc = 0.f;
#pragma unroll
        for (int c = 0; c < 8; c++) acc = fmaf(s_qd[w][c], s_mkT[c][l], acc);
        float ph = acc * PI_F;
        float s4, c4, sh, ch;
        __sincosf(0.25f * ph, &s4, &c4);
        __sincosf(0.50f * ph, &sh, &ch);
        float cc2 = c4 * c4, ss2 = s4 * s4, cs2 = c4 * s4;
        float2 e0 = make_float2(ch, -sh);
        float2 e1 = make_float2(ch,  sh);
        float2 u0 = cmul(e0, make_float2(cc2,  ss2));
        float2 u1 = cmul(e0, make_float2(-cs2, -cs2));
        float2 u2 = cmul(e1, make_float2(cs2,  -cs2));
        float2 u3 = cmul(e1, make_float2(cc2,  -ss2));

        float2 v[8];
#pragma unroll
        for (int e = 0; e < 8; e++) v[e] = s_phivT[e][l];
#pragma unroll
        for (int q = 0; q < 3; q++) {
            int p = 2 - q;
#pragma unroll
            for (int k = 0; k < 8; k++) {
                if ((k >> p) & 1) continue;
                int k1 = k | (1 << p);
                float2 v0 = v[k], v1 = v[k1];
                v[k]  = cadd(cmul(u0, v0), cmul(u1, v1));
                v[k1] = cadd(cmul(u2, v0), cmul(u3, v1));
            }
        }
        float n0 = fmaf(v[0].x, v[0].x, v[0].y * v[0].y)
                 + fmaf(v[3].x, v[3].x, v[3].y * v[3].y)
                 + fmaf(v[5].x, v[5].x, v[5].y * v[5].y)
                 + fmaf(v[6].x, v[6].x, v[6].y * v[6].y);
        float n1 = fmaf(v[1].x, v[1].x, v[1].y * v[1].y)
                 + fmaf(v[2].x, v[2].x, v[2].y * v[2].y)
                 + fmaf(v[4].x, v[4].x, v[4].y * v[4].y)
                 + fmaf(v[7].x, v[7].x, v[7].y * v[7].y);
        float2 V01 = make_float2(0.f, 0.f), V11 = make_float2(0.f, 0.f);
        V01 = cadd(V01, cmulc(v[0], v[4]));
        V01 = cadd(V01, cmulc(v[3], v[7]));
        V01 = cadd(V01, cmulc(v[5], v[1]));
        V01 = cadd(V01, cmulc(v[6], v[2]));
        V11 = cadd(V11, cmulc(v[1], v[5]));
        V11 = cadd(V11, cmulc(v[2], v[6]));
        V11 = cadd(V11, cmulc(v[4], v[0]));
        V11 = cadd(V11, cmulc(v[7], v[3]));
        s_V4[w][l][0] = make_float4(n0, 0.f, V01.x, V01.y);
        s_V4[w][l][1] = make_float4(n1, 0.f, V11.x, V11.y);
        if (l == 0) {
#pragma unroll
            for (int e = 0; e < 8; e++) s_chi0[w][e] = v[e];
        }
    }
    __syncwarp();

    // ---- Phase 6: drifting-coordinate register scan ----
    int selA0[4], selA1[4];
    {
        int m = l;
        int p1 = Pmap(m), p2 = Pmap(p1), p3 = Pmap(p2);
        selA0[0] = (((m  >> 3) & 1) << 1) | ((((m  >> 3) ^ m ) & 1));
        selA0[1] = (((p3 >> 3) & 1) << 1) | ((((p3 >> 3) ^ p3) & 1));
        selA0[2] = (((p2 >> 3) & 1) << 1) | ((((p2 >> 3) ^ p2) & 1));
        selA0[3] = (((p1 >> 3) & 1) << 1) | ((((p1 >> 3) ^ p1) & 1));
        m = l + 32;
        p1 = Pmap(m); p2 = Pmap(p1); p3 = Pmap(p2);
        selA1[0] = (((m  >> 3) & 1) << 1) | ((((m  >> 3) ^ m ) & 1));
        selA1[1] = (((p3 >> 3) & 1) << 1) | ((((p3 >> 3) ^ p3) & 1));
        selA1[2] = (((p2 >> 3) & 1) << 1) | ((((p2 >> 3) ^ p2) & 1));
        selA1[3] = (((p1 >> 3) & 1) << 1) | ((((p1 >> 3) ^ p1) & 1));
    }
    const int dmarr[4] = {4, 22, 13, 31};

    float2 r0, r1;
    {
        float2 ca  = s_chi0[w][l >> 3];
        float2 ca1 = s_chi0[w][4 + (l >> 3)];
        float2 cc  = s_chi0[w][l & 7];
        r0 = cmulc(ca, cc);
        r1 = cmulc(ca1, cc);
    }

#pragma unroll
    for (int j = 1; j < SEQ; j++) {
        const int k  = j & 3;
        const int dm = dmarr[k];
        float4 va = s_V4[w][j][0];
        float4 vb = s_V4[w][j][1];
        float2 v00 = make_float2(va.x, va.y), v01 = make_float2(va.z, va.w);
        float2 v10 = make_float2(vb.x, vb.y), v11 = make_float2(vb.z, vb.w);

        float2 p0 = shfl2(r1, dm);
        float2 p1 = shfl2(r0, dm);

        int s0 = selA0[k];
        float2 g0a = (s0 & 1) ? v01 : v00;
        float2 g0b = (s0 & 1) ? v11 : v10;
        float2 VA0 = (s0 & 2) ? g0b : g0a;
        float2 VB0 = (s0 & 2) ? g0a : g0b;
        int s1 = selA1[k];
        float2 g1a = (s1 & 1) ? v01 : v00;
        float2 g1b = (s1 & 1) ? v11 : v10;
        float2 VA1 = (s1 & 2) ? g1b : g1a;
        float2 VB1 = (s1 & 2) ? g1a : g1b;

        float2 n0 = cmul(r0, VA0); cmac(n0, p0, VB0);
        float2 n1 = cmul(r1, VA1); cmac(n1, p1, VB1);
        r0 = n0; r1 = n1;
    }

    // undrift + diagonal
    s_fin[w][l]      = r0.x;
    s_fin[w][l + 32] = r1.x;
    __syncwarp();
    if (l < 8) {
        int mm = Pmap(Pmap(Pmap(l * 9)));
        s_z[w][l] = s_fin[w][mm];
    }
    __syncwarp();

    // ---- Phase 7: distributed output accumulation (per warp = row i) ----
    {
        const int i = i0 + w;
        float zr[8];
#pragma unroll
        for (int e = 0; e < 8; e++) zr[e] = s_z[w][e];   // broadcast LDS

        // partials for d = l and d = l+32
        const float4* w2a = (const float4*)(W2 + l * DM + h * DK);
        const float4* w2b = (const float4*)(W2 + (l + 32) * DM + h * DK);
        float4 wa0 = w2a[0], wa1 = w2a[1];
        float4 wb0 = w2b[0], wb1 = w2b[1];
        float p0 = zr[0] * wa0.x + zr[1] * wa0.y + zr[2] * wa0.z + zr[3] * wa0.w
                 + zr[4] * wa1.x + zr[5] * wa1.y + zr[6] * wa1.z + zr[7] * wa1.w;
        float p1 = zr[0] * wb0.x + zr[1] * wb0.y + zr[2] * wb0.z + zr[3] * wb0.w
                 + zr[4] * wb1.x + zr[5] * wb1.y + zr[6] * wb1.z + zr[7] * wb1.w;

        float* o0 = out + i * DM + l;
        float* o1 = out + i * DM + l + 32;

        if (h == 0) {
            p0 += b2[l];
            p1 += b2[l + 32];
            atomicExch(o0, p0);              // L2-level init (overwrites poison)
            atomicExch(o1, p1);
            __threadfence();
            __syncwarp();
            if (l == 0) atomicExch(&g_flag[i], 1u);
        } else {
            if (l == 0) {
                while (atomicAdd(&g_flag[i], 0u) == 0u) { }
            }
            __syncwarp();
            atomicAdd(o0, p0);
            atomicAdd(o1, p1);
            __syncwarp();
            if (l == 0) {
                unsigned c = atomicAdd(&g_done[i], 1u);
                if (c == 6u) {               // 7th adder: reset for next replay
                    atomicExch(&g_flag[i], 0u);
                    atomicExch(&g_done[i], 0u);
                }
            }
        }
    }
}

extern "C" void kernel_launch(void* const* d_in, const int* in_sizes, int n_in,
                              void* d_out, int out_size) {
    const float* x    = (const float*)d_in[0];
    const float* pqc  = (const float*)d_in[1];
    const float* W1   = (const float*)d_in[2];
    const float* b1   = (const float*)d_in[3];
    const float* W2   = (const float*)d_in[4];
    const float* b2   = (const float*)d_in[5];
    float* out = (float*)d_out;

    qfused<<<GRID, 128>>>(x, pqc, W1, b1, W2, b2, out);
}

// round 9
// speedup vs baseline: 2.3333x; 1.2143x over previous
#include <cuda_runtime.h>
#include <math.h>

#define NH 8
#define SEQ 32
#define DK 8
#define DM 64
#define PI_F 3.14159265358979323846f
#define W_MUL 0.6324555320336759f  // sqrt(2/5)

#define XPAD 68          // padded x/W1 stage row (floats)

__device__ __forceinline__ float2 cmul(float2 a, float2 b) {
    return make_float2(fmaf(a.x, b.x, -a.y * b.y), fmaf(a.x, b.y, a.y * b.x));
}
// a * conj(b)
__device__ __forceinline__ float2 cmulc(float2 a, float2 b) {
    return make_float2(fmaf(a.x, b.x, a.y * b.y), fmaf(a.y, b.x, -a.x * b.y));
}
__device__ __forceinline__ float2 cadd(float2 a, float2 b) {
    return make_float2(a.x + b.x, a.y + b.y);
}
// acc += a*b
__device__ __forceinline__ void cmac(float2& acc, float2 a, float2 b) {
    acc.x = fmaf(a.x, b.x, fmaf(-a.y, b.y, acc.x));
    acc.y = fmaf(a.x, b.y, fmaf( a.y, b.x, acc.y));
}

// CNOT-ring basis permutation f(x) (sign table only)
__device__ __forceinline__ int permf(int x) {
#pragma unroll
    for (int t = 0; t < 6; t++) {
        int cb = 5 - t;
        int tb = 5 - ((t + 1) % 6);
        if ((x >> cb) & 1) x ^= (1 << tb);
    }
    return x;
}

// flat-64 gather permutation: P(m) = r(m>>3)*8 + r(m&7), r(a)=a^(a>>1). order 4.
__device__ __forceinline__ int Pmap(int m) {
    int a = m >> 3, c = m & 7;
    int ra = (a ^ (a >> 1)) & 7;
    int rc = (c ^ (c >> 1)) & 7;
    return ra * 8 + rc;
}

__device__ __forceinline__ void apply_u3(const float2 (*u)[4], const float* psi,
                                         float2* v) {
#pragma unroll
    for (int e = 0; e < 8; e++) v[e] = make_float2(psi[e], 0.f);
#pragma unroll
    for (int q = 0; q < 3; q++) {
        int p = 2 - q;
        float2 u0 = u[q][0], u1 = u[q][1], u2 = u[q][2], u3 = u[q][3];
#pragma unroll
        for (int k = 0; k < 8; k++) {
            if ((k >> p) & 1) continue;
            int k1 = k | (1 << p);
            float2 v0 = v[k], v1 = v[k1];
            v[k]  = cadd(cmul(u0, v0), cmul(u1, v1));
            v[k1] = cadd(cmul(u2, v0), cmul(u3, v1));
        }
    }
}

__device__ __forceinline__ float2 shfl2(float2 v, int m) {
    return make_float2(__shfl_xor_sync(0xffffffffu, v.x, m),
                       __shfl_xor_sync(0xffffffffu, v.y, m));
}

// grid = 32 (block = sequence row i), block = 256 (warp w = head h)
__global__ void __launch_bounds__(256)
qfused(const float* __restrict__ x,     // (32,64)
       const float* __restrict__ pqc,   // (8,3,9)
       const float* __restrict__ W1,    // (8,64)
       const float* __restrict__ b1,    // (8,)
       const float* __restrict__ W2,    // (64,64)
       const float* __restrict__ b2,    // (64,)
       float* __restrict__ out)         // (1,32,64)
{
    const int i = blockIdx.x;        // sequence row
    const int t = threadIdx.x;       // 0..255
    const int w = t >> 5;            // warp = head
    const int l = t & 31;

    __shared__ float  s_xs [SEQ][XPAD];       // staged x
    __shared__ float  s_ws [DK][XPAD];        // staged W1
    __shared__ float  s_xq [SEQ][9];
    __shared__ float  s_psi[SEQ][9];
    __shared__ float2 s_u[NH][3][3][4];       // per-head unitaries
    __shared__ float  s_ms[64];
    __shared__ float4 s_V4[NH][SEQ][2];
    __shared__ float2 s_chi0[NH][8];
    __shared__ float  s_fin[NH][64];
    __shared__ float  s_z[NH][8];
    __shared__ float  s_part[NH][65];         // padded per-head partials

    // ---- Phase 0: tables + stage x/W1 + per-head unitaries ----
    if (t < 64) s_ms[t] = (__popc(permf(t)) & 1) ? -1.0f : 1.0f;
    {
        const float4* xs = (const float4*)x;
#pragma unroll
        for (int k = 0; k < 2; k++) {
            int q = t + 256 * k;          // 0..511
            int s = q >> 4, j = q & 15;
            *(float4*)&s_xs[s][4 * j] = xs[q];
        }
        if (t < 128) {
            int c = t >> 4, j = t & 15;
            *(float4*)&s_ws[c][4 * j] = ((const float4*)W1)[t];
        }
    }
    if (l < 9) {                          // warp w builds head w's 9 unitaries
        int g = l / 3, q = l % 3;
        const float* ap = pqc + w * 27 + g * 9 + q * 3;
        float a0 = ap[0] * W_MUL, a1 = ap[1] * W_MUL, a2 = ap[2] * W_MUL;
        float sx, cx, sy, cy, sz, cz;
        __sincosf(0.5f * a0, &sx, &cx);
        __sincosf(0.5f * a1, &sy, &cy);
        __sincosf(0.5f * a2, &sz, &cz);
        float2 m00 = make_float2(cy * cx,   sy * sx);
        float2 m01 = make_float2(-sy * cx, -cy * sx);
        float2 m10 = make_float2(sy * cx,  -cy * sx);
        float2 m11 = make_float2(cy * cx,  -sy * sx);
        float2 e0 = make_float2(cz, -sz);
        float2 e1 = make_float2(cz,  sz);
        s_u[w][g][q][0] = cmul(e0, m00);
        s_u[w][g][q][1] = cmul(e0, m01);
        s_u[w][g][q][2] = cmul(e1, m10);
        s_u[w][g][q][3] = cmul(e1, m11);
    }
    __syncthreads();

    // ---- Phase 1: xq = x @ W1^T + b1 (1 output/thread) ----
    {
        const int c = t & 7;
        const int s = t >> 3;             // 0..31
        float a0 = b1[c];
        const float4* wr = (const float4*)&s_ws[c][0];
        const float4* xr = (const float4*)&s_xs[s][0];
#pragma unroll
        for (int j = 0; j < 16; j++) {
            float4 wv = wr[j];
            float4 v0 = xr[j];
            a0 = fmaf(v0.x, wv.x, fmaf(v0.y, wv.y, fmaf(v0.z, wv.z, fmaf(v0.w, wv.w, a0))));
        }
        s_xq[s][c] = a0;
    }
    __syncthreads();

    // ---- Phase 2: normalize (1 output/thread) ----
    {
        int s = t >> 3, c = t & 7;
        float n = 0.f;
#pragma unroll
        for (int e = 0; e < DK; e++) n = fmaf(s_xq[s][e], s_xq[s][e], n);
        s_psi[s][c] = s_xq[s][c] * rsqrtf(n);
    }
    __syncthreads();

    // ============ everything below is warp-local (head h = w) ============

    // ---- Phase 3: lane l computes kd_l, phiv_l, qd (all registers) ----
    float kd[8], qd[8];
    float2 pv[8];
    {
        float2 vk[8];
        apply_u3(s_u[w][1], &s_psi[l][0], vk);
#pragma unroll
        for (int e = 0; e < 8; e++)
            kd[e] = fmaf(vk[e].x, vk[e].x, vk[e].y * vk[e].y);
        apply_u3(s_u[w][2], &s_psi[l][0], pv);
        float2 vq[8];
        apply_u3(s_u[w][0], &s_psi[i][0], vq);   // broadcast read
#pragma unroll
        for (int e = 0; e < 8; e++)
            qd[e] = fmaf(vq[e].x, vq[e].x, vq[e].y * vq[e].y);
    }

    // ---- Phase 4: phi_l = pi * sum_{c,d} ms[8c+d] qd[c] kd[d] ----
    float ph;
    {
        float acc = 0.f;
#pragma unroll
        for (int c = 0; c < 8; c++) {
            float mk = 0.f;
#pragma unroll
            for (int d = 0; d < 8; d++)
                mk = fmaf(s_ms[c * 8 + d], kd[d], mk);    // broadcast LDS
            acc = fmaf(qd[c], mk, acc);
        }
        ph = acc * PI_F;
    }

    // ---- Phase 5: chi_l = Uw(phi_l) phiv_l;  V row ----
    {
        float s4, c4, sh, ch;
        __sincosf(0.25f * ph, &s4, &c4);
        __sincosf(0.50f * ph, &sh, &ch);
        float cc2 = c4 * c4, ss2 = s4 * s4, cs2 = c4 * s4;
        float2 e0 = make_float2(ch, -sh);
        float2 e1 = make_float2(ch,  sh);
        float2 u0 = cmul(e0, make_float2(cc2,  ss2));
        float2 u1 = cmul(e0, make_float2(-cs2, -cs2));
        float2 u2 = cmul(e1, make_float2(cs2,  -cs2));
        float2 u3 = cmul(e1, make_float2(cc2,  -ss2));

        float2 v[8];
#pragma unroll
        for (int e = 0; e < 8; e++) v[e] = pv[e];
#pragma unroll
        for (int q = 0; q < 3; q++) {
            int p = 2 - q;
#pragma unroll
            for (int k = 0; k < 8; k++) {
                if ((k >> p) & 1) continue;
                int k1 = k | (1 << p);
                float2 v0 = v[k], v1 = v[k1];
                v[k]  = cadd(cmul(u0, v0), cmul(u1, v1));
                v[k1] = cadd(cmul(u2, v0), cmul(u3, v1));
            }
        }
        float n0 = fmaf(v[0].x, v[0].x, v[0].y * v[0].y)
                 + fmaf(v[3].x, v[3].x, v[3].y * v[3].y)
                 + fmaf(v[5].x, v[5].x, v[5].y * v[5].y)
                 + fmaf(v[6].x, v[6].x, v[6].y * v[6].y);
        float n1 = fmaf(v[1].x, v[1].x, v[1].y * v[1].y)
                 + fmaf(v[2].x, v[2].x, v[2].y * v[2].y)
                 + fmaf(v[4].x, v[4].x, v[4].y * v[4].y)
                 + fmaf(v[7].x, v[7].x, v[7].y * v[7].y);
        float2 V01 = make_float2(0.f, 0.f), V11 = make_float2(0.f, 0.f);
        V01 = cadd(V01, cmulc(v[0], v[4]));
        V01 = cadd(V01, cmulc(v[3], v[7]));
        V01 = cadd(V01, cmulc(v[5], v[1]));
        V01 = cadd(V01, cmulc(v[6], v[2]));
        V11 = cadd(V11, cmulc(v[1], v[5]));
        V11 = cadd(V11, cmulc(v[2], v[6]));
        V11 = cadd(V11, cmulc(v[4], v[0]));
        V11 = cadd(V11, cmulc(v[7], v[3]));
        s_V4[w][l][0] = make_float4(n0, 0.f, V01.x, V01.y);
        s_V4[w][l][1] = make_float4(n1, 0.f, V11.x, V11.y);
        if (l == 0) {
#pragma unroll
            for (int e = 0; e < 8; e++) s_chi0[w][e] = v[e];
        }
    }
    __syncwarp();

    // ---- Phase 6: drifting-coordinate register scan ----
    int selA0[4], selA1[4];
    {
        int m = l;
        int p1 = Pmap(m), p2 = Pmap(p1), p3 = Pmap(p2);
        selA0[0] = (((m  >> 3) & 1) << 1) | ((((m  >> 3) ^ m ) & 1));
        selA0[1] = (((p3 >> 3) & 1) << 1) | ((((p3 >> 3) ^ p3) & 1));
        selA0[2] = (((p2 >> 3) & 1) << 1) | ((((p2 >> 3) ^ p2) & 1));
        selA0[3] = (((p1 >> 3) & 1) << 1) | ((((p1 >> 3) ^ p1) & 1));
        m = l + 32;
        p1 = Pmap(m); p2 = Pmap(p1); p3 = Pmap(p2);
        selA1[0] = (((m  >> 3) & 1) << 1) | ((((m  >> 3) ^ m ) & 1));
        selA1[1] = (((p3 >> 3) & 1) << 1) | ((((p3 >> 3) ^ p3) & 1));
        selA1[2] = (((p2 >> 3) & 1) << 1) | ((((p2 >> 3) ^ p2) & 1));
        selA1[3] = (((p1 >> 3) & 1) << 1) | ((((p1 >> 3) ^ p1) & 1));
    }
    const int dmarr[4] = {4, 22, 13, 31};

    float2 r0, r1;
    {
        float2 ca  = s_chi0[w][l >> 3];
        float2 ca1 = s_chi0[w][4 + (l >> 3)];
        float2 cc  = s_chi0[w][l & 7];
        r0 = cmulc(ca, cc);
        r1 = cmulc(ca1, cc);
    }

#pragma unroll
    for (int j = 1; j < SEQ; j++) {
        const int k  = j & 3;
        const int dm = dmarr[k];
        float4 va = s_V4[w][j][0];
        float4 vb = s_V4[w][j][1];
        float2 v00 = make_float2(va.x, va.y), v01 = make_float2(va.z, va.w);
        float2 v10 = make_float2(vb.x, vb.y), v11 = make_float2(vb.z, vb.w);

        float2 p0 = shfl2(r1, dm);
        float2 p1 = shfl2(r0, dm);

        int s0 = selA0[k];
        float2 g0a = (s0 & 1) ? v01 : v00;
        float2 g0b = (s0 & 1) ? v11 : v10;
        float2 VA0 = (s0 & 2) ? g0b : g0a;
        float2 VB0 = (s0 & 2) ? g0a : g0b;
        int s1 = selA1[k];
        float2 g1a = (s1 & 1) ? v01 : v00;
        float2 g1b = (s1 & 1) ? v11 : v10;
        float2 VA1 = (s1 & 2) ? g1b : g1a;
        float2 VB1 = (s1 & 2) ? g1a : g1b;

        float2 n0 = cmul(r0, VA0); cmac(n0, p0, VB0);
        float2 n1 = cmul(r1, VA1); cmac(n1, p1, VB1);
        r0 = n0; r1 = n1;
    }

    // undrift + diagonal
    s_fin[w][l]      = r0.x;
    s_fin[w][l + 32] = r1.x;
    __syncwarp();
    if (l < 8) {
        int mm = Pmap(Pmap(Pmap(l * 9)));
        s_z[w][l] = s_fin[w][mm];
    }
    __syncwarp();

    // ---- Phase 7: per-head output partials ----
    {
        float zr[8];
#pragma unroll
        for (int e = 0; e < 8; e++) zr[e] = s_z[w][e];   // broadcast LDS

        const float4* w2a = (const float4*)(W2 + l * DM + w * DK);
        const float4* w2b = (const float4*)(W2 + (l + 32) * DM + w * DK);
        float4 wa0 = w2a[0], wa1 = w2a[1];
        float4 wb0 = w2b[0], wb1 = w2b[1];
        float p0 = zr[0] * wa0.x + zr[1] * wa0.y + zr[2] * wa0.z + zr[3] * wa0.w
                 + zr[4] * wa1.x + zr[5] * wa1.y + zr[6] * wa1.z + zr[7] * wa1.w;
        float p1 = zr[0] * wb0.x + zr[1] * wb0.y + zr[2] * wb0.z + zr[3] * wb0.w
                 + zr[4] * wb1.x + zr[5] * wb1.y + zr[6] * wb1.z + zr[7] * wb1.w;
        s_part[w][l]      = p0;
        s_part[w][l + 32] = p1;
    }
    __syncthreads();

    // ---- Phase 8: cross-head reduction, write out row i ----
    if (t < 64) {
        float acc = b2[t];
#pragma unroll
        for (int hh = 0; hh < NH; hh++) acc += s_part[hh][t];
        out[i * DM + t] = acc;
    }
}

extern "C" void kernel_launch(void* const* d_in, const int* in_sizes, int n_in,
                              void* d_out, int out_size) {
    const float* x    = (const float*)d_in[0];
    const float* pqc  = (const float*)d_in[1];
    const float* W1   = (const float*)d_in[2];
    const float* b1   = (const float*)d_in[3];
    const float* W2   = (const float*)d_in[4];
    const float* b2   = (const float*)d_in[5];
    float* out = (float*)d_out;

    qfused<<<SEQ, 256>>>(x, pqc, W1, b1, W2, b2, out);
}